// round 15
// baseline (speedup 1.0000x reference)
#include <cuda_runtime.h>
#include <cstdint>

// GraphPool: out[s,a,f] = (deg(s,a)>0) * max over {a} ∪ {e in edges[s,a,:], e>=0} of atoms[s,e,f]
// S=512, A=128, F=128, D=6.  Edges arrive as int32.
//
// One CTA per s. atoms[s] tile (64KB) via cp.async.bulk (TMA); edges staged
// into 32B-padded smem rows during TMA flight (1 LDS.128 + 1 LDS.64 broadcast
// per row). Mainloop: software-pipelined edge prefetch (next row's edges
// loaded during current row's gathers), branchless clamp-to-self gather,
// 7 batched LDS.128, 3-deep fmax tree, mask via max(e)>=0.
//
// 256 thr / 3 CTAs/SM -> 84-reg budget: prefetch regs + 7-wide batch fit.

#define S_DIM 512
#define A_DIM 128
#define F_DIM 128
#define D_DIM 6
#define F4      (F_DIM / 4)            // 32 float4 per row
#define TILE_F4 (A_DIM * F4)           // 4096 float4 = 64KB
#define TILE_BYTES (TILE_F4 * 16)
#define NEDGE   (A_DIM * D_DIM)        // 768 ints
#define NTHR 256
#define NWARP (NTHR / 32)              // 8 warps, 16 rows each

// smem layout: [0:8) mbarrier | [128:128+4096) padded edges (128 rows x 32B)
//              | [4224 : +64KB) tile
#define SM_EDGE_OFF 128
#define SM_TILE_OFF (SM_EDGE_OFF + A_DIM * 32)   // 4224, 16B-aligned
#define SMEM_BYTES  (SM_TILE_OFF + TILE_BYTES)   // 69760 (x3 = 209KB < 228KB)

__device__ __forceinline__ uint32_t smem_u32(const void* p) {
    uint32_t a;
    asm("{ .reg .u64 t; cvta.to.shared.u64 t, %1; cvt.u32.u64 %0, t; }" : "=r"(a) : "l"(p));
    return a;
}

__device__ __forceinline__ float4 fmax4(float4 a, float4 b) {
    return make_float4(fmaxf(a.x, b.x), fmaxf(a.y, b.y),
                       fmaxf(a.z, b.z), fmaxf(a.w, b.w));
}

__global__ __launch_bounds__(NTHR, 3)
void graphpool_kernel(const float* __restrict__ atoms,
                      const int* __restrict__ edges,
                      float* __restrict__ out) {
    extern __shared__ __align__(128) char smem[];
    uint32_t smem_base = smem_u32(smem);
    char*   epad = smem + SM_EDGE_OFF;               // 32B rows
    const float4* tile = reinterpret_cast<const float4*>(smem + SM_TILE_OFF);

    const int s   = blockIdx.x;
    const int tid = threadIdx.x;
    const uint32_t mbar = smem_base;
    const uint32_t tile_sm = smem_base + SM_TILE_OFF;

    if (tid == 0) {
        asm volatile("mbarrier.init.shared.b64 [%0], 1;" :: "r"(mbar) : "memory");
    }
    __syncthreads();

    if (tid == 0) {
        asm volatile("fence.proxy.async.shared::cta;" ::: "memory");
        asm volatile("mbarrier.arrive.expect_tx.shared.b64 _, [%0], %1;"
                     :: "r"(mbar), "r"((uint32_t)TILE_BYTES) : "memory");
        const float* src = atoms + (size_t)s * (A_DIM * F_DIM);
        asm volatile(
            "cp.async.bulk.shared::cta.global.mbarrier::complete_tx::bytes "
            "[%0], [%1], %2, [%3];"
            :: "r"(tile_sm), "l"(src), "r"((uint32_t)TILE_BYTES), "r"(mbar)
            : "memory");
    }

    // Stage edges into 32B-padded rows while the bulk copy is in flight.
    // Row r: 6 ints at global offset r*24B (8B aligned) -> smem row r*32B.
    if (tid < A_DIM) {
        const int* gr = edges + (size_t)s * NEDGE + tid * D_DIM;
        const int2 x0 = *reinterpret_cast<const int2*>(gr);
        const int2 x1 = *reinterpret_cast<const int2*>(gr + 2);
        const int2 x2 = *reinterpret_cast<const int2*>(gr + 4);
        char* er = epad + tid * 32;
        *reinterpret_cast<int4*>(er)     = make_int4(x0.x, x0.y, x1.x, x1.y);
        *reinterpret_cast<int2*>(er + 16) = x2;
    }
    __syncthreads();

    // Wait for the tile (phase 0).
    {
        uint32_t done;
        asm volatile(
            "{\n\t.reg .pred p;\n\t"
            "mbarrier.try_wait.parity.acquire.cta.shared::cta.b64 p, [%1], 0;\n\t"
            "selp.b32 %0, 1, 0, p;\n\t}"
            : "=r"(done) : "r"(mbar) : "memory");
        if (!done) {
            asm volatile(
                "{\n\t.reg .pred P1;\n\t"
                "WL_%=:\n\t"
                "mbarrier.try_wait.parity.acquire.cta.shared::cta.b64 P1, [%0], 0, 0x989680;\n\t"
                "@P1 bra.uni WD_%=;\n\t"
                "bra.uni WL_%=;\n\t"
                "WD_%=:\n\t}"
                :: "r"(mbar) : "memory");
        }
    }

    const int lane = tid & 31;
    const int warp = tid >> 5;

    float4* gout = reinterpret_cast<float4*>(out) + (size_t)s * TILE_F4;

    // Software-pipelined edge prefetch: load row a's edges one iteration early.
    int4 pe0 = *reinterpret_cast<const int4*>(epad + warp * 32);
    int2 pe1 = *reinterpret_cast<const int2*>(epad + warp * 32 + 16);

#pragma unroll 2
    for (int a = warp; a < A_DIM; a += NWARP) {
        const int4 E0 = pe0;
        const int2 E1 = pe1;

        // Prefetch next row's edges (wrap-around keeps it branchless & in-bounds).
        const int an = (a + NWARP) & (A_DIM - 1);
        pe0 = *reinterpret_cast<const int4*>(epad + an * 32);
        pe1 = *reinterpret_cast<const int2*>(epad + an * 32 + 16);

        // deg==0  <=>  all edges -1  <=>  max(e) < 0
        const int emax = max(max(max(E0.x, E0.y), max(E0.z, E0.w)),
                             max(E1.x, E1.y));
        const float m = (emax >= 0) ? 1.0f : 0.0f;

        // Branchless: clamp missing edges to self row (fmax no-op).
        const int i0 = (E0.x < 0) ? a : E0.x;
        const int i1 = (E0.y < 0) ? a : E0.y;
        const int i2 = (E0.z < 0) ? a : E0.z;
        const int i3 = (E0.w < 0) ? a : E0.w;
        const int i4 = (E1.x < 0) ? a : E1.x;
        const int i5 = (E1.y < 0) ? a : E1.y;

        // 7 independent gathers, 3-deep fmax tree.
        const float4 gs = tile[a  * F4 + lane];
        const float4 g0 = tile[i0 * F4 + lane];
        const float4 g1 = tile[i1 * F4 + lane];
        const float4 g2 = tile[i2 * F4 + lane];
        const float4 g3 = tile[i3 * F4 + lane];
        const float4 g4 = tile[i4 * F4 + lane];
        const float4 g5 = tile[i5 * F4 + lane];

        float4 v = fmax4(fmax4(fmax4(gs, g0), fmax4(g1, g2)),
                         fmax4(fmax4(g3, g4), g5));

        v.x *= m; v.y *= m; v.z *= m; v.w *= m;

        gout[a * F4 + lane] = v;               // coalesced 512B per warp
    }
}

extern "C" void kernel_launch(void* const* d_in, const int* in_sizes, int n_in,
                              void* d_out, int out_size) {
    const float* atoms = (const float*)d_in[0];
    const int*   edges = (const int*)d_in[1];
    float*       out   = (float*)d_out;

    cudaFuncSetAttribute(graphpool_kernel,
                         cudaFuncAttributeMaxDynamicSharedMemorySize, SMEM_BYTES);

    graphpool_kernel<<<S_DIM, NTHR, SMEM_BYTES>>>(atoms, edges, out);
}